// round 12
// baseline (speedup 1.0000x reference)
#include <cuda_runtime.h>

#define DM 24
#define RD 10
#define NSEQ 512
#define NBATCH 8
#define ROWS (NBATCH * NSEQ)          // 4096
#define APAD 12
#define CQS 52                        // padded row stride for staged cj/qj
#define JCH 128                       // j-chunk rows per superiter

typedef unsigned long long u64;

// Scratch (no runtime allocation allowed)
__device__ __align__(16) float g_A[ROWS * APAD];    // x_i @ W1[0:24] + b1
__device__ __align__(16) float g_Bv[ROWS * APAD];   // x_j @ W1[24:48]

// ---------------- f32x2 helpers ----------------
__device__ __forceinline__ u64 pk(float lo, float hi) {
    u64 r; asm("mov.b64 %0, {%1, %2};" : "=l"(r) : "f"(lo), "f"(hi)); return r;
}
__device__ __forceinline__ void upk(float& lo, float& hi, u64 v) {
    asm("mov.b64 {%0, %1}, %2;" : "=f"(lo), "=f"(hi) : "l"(v));
}
__device__ __forceinline__ u64 f2fma(u64 a, u64 b, u64 c) {
    u64 d; asm("fma.rn.f32x2 %0, %1, %2, %3;" : "=l"(d) : "l"(a), "l"(b), "l"(c)); return d;
}
__device__ __forceinline__ u64 f2add(u64 a, u64 b) {
    u64 d; asm("add.rn.f32x2 %0, %1, %2;" : "=l"(d) : "l"(a), "l"(b)); return d;
}

// ---------------------------------------------------------------------------
// Kernel 1: per-row precompute (vectorized x loads)
// ---------------------------------------------------------------------------
__global__ void precompute_kernel(const float* __restrict__ x,
                                  const float* __restrict__ W1,
                                  const float* __restrict__ b1) {
    int row = blockIdx.x * blockDim.x + threadIdx.x;
    if (row >= ROWS) return;
    float xv[DM];
    {
        const float4* x4 = (const float4*)(x + (size_t)row * DM);
#pragma unroll
        for (int k = 0; k < 6; k++) {
            float4 t = x4[k];
            xv[4*k] = t.x; xv[4*k+1] = t.y; xv[4*k+2] = t.z; xv[4*k+3] = t.w;
        }
    }
    float A[RD], Bv[RD];
#pragma unroll
    for (int r = 0; r < RD; r++) { A[r] = b1[r]; Bv[r] = 0.f; }
#pragma unroll
    for (int d = 0; d < DM; d++) {
        float xd = xv[d];
#pragma unroll
        for (int r = 0; r < RD; r++) {
            A[r]  = fmaf(xd, W1[d * RD + r], A[r]);
            Bv[r] = fmaf(xd, W1[(DM + d) * RD + r], Bv[r]);
        }
    }
#pragma unroll
    for (int r = 0; r < RD; r++) {
        g_A[row * APAD + r]  = A[r];
        g_Bv[row * APAD + r] = Bv[r];
    }
    g_A[row * APAD + 10] = 0.f;  g_A[row * APAD + 11] = 0.f;
    g_Bv[row * APAD + 10] = 0.f; g_Bv[row * APAD + 11] = 0.f;
}

// ---------------------------------------------------------------------------
// Kernel 2: pairwise. 4 warps/block, 1 warp per i, 128-row staged j-chunk.
// Per superiter the 4 lane-j's are processed in TWO x-passes of 2 to cap
// register pressure (no spills) and allow 5 blocks/SM.
// ---------------------------------------------------------------------------
__global__ __launch_bounds__(128, 5)
void pair_kernel(const float* __restrict__ q,
                 const float* __restrict__ coord,
                 const float* __restrict__ W1,
                 const float* __restrict__ W2,
                 const float* __restrict__ b2,
                 float* __restrict__ out) {
    __shared__ __align__(16) float s_cq[JCH][CQS];  // [r][0:24)=coord_j, [24:48)=q_j (208B stride)
    __shared__ __align__(16) float s_bj[JCH][14];   // B_j rows (56B stride; float2/u64 access only)
    __shared__ __align__(16) float s_w1[26][12];    // [k][r]: k<24 |cdiff| rows, 24=qov, 25=dist
    __shared__ __align__(16) float s_w2[10][12];    // [rh][c] = W2[rh][c]
    __shared__ __align__(16) float s_ciq[4][CQS];   // per-warp: ci (0..23), qi (24..47)
    __shared__ __align__(16) float s_ai[4][12];     // per-warp: A_i

    const int tid = threadIdx.x;
    const int w = tid >> 5, lane = tid & 31;
    const int i = blockIdx.x * 4 + w;
    const int jbase = i & ~(NSEQ - 1);

    // --- one-time fills ---
    for (int idx = tid; idx < 26 * 12; idx += 128) {
        int d = idx / 12, r = idx % 12;
        float v = 0.f;
        if (r < RD) {
            int row = (d < 24) ? (48 + d) : (d == 24 ? 72 : 73);
            v = W1[row * RD + r];
        }
        s_w1[d][r] = v;
    }
    for (int idx = tid; idx < 10 * 12; idx += 128) {
        int rh = idx / 12, c = idx % 12;
        s_w2[rh][c] = (c < RD) ? W2[rh * RD + c] : 0.f;
    }
    if (lane < DM) {
        s_ciq[w][lane]      = coord[(size_t)i * DM + lane];
        s_ciq[w][24 + lane] = q[(size_t)i * DM + lane];
    }
    if (lane < 12) s_ai[w][lane] = g_A[i * APAD + lane];

    float sacc[RD], macc[RD];
#pragma unroll
    for (int c = 0; c < RD; c++) { sacc[c] = 0.f; macc[c] = 0.f; }

    for (int it = 0; it < NSEQ / JCH; ++it) {
        const int jb = jbase + it * JCH;
        __syncthreads();
        // --- stage 128 j-rows (coalesced) ---
        {
            const float4* gc = (const float4*)(coord + (size_t)jb * DM);
            const float4* gq = (const float4*)(q + (size_t)jb * DM);
#pragma unroll
            for (int k = tid; k < JCH * 6; k += 128) {       // 768
                int r = k / 6, c = (k % 6) * 4;
                *(float4*)&s_cq[r][c]      = gc[k];
                *(float4*)&s_cq[r][24 + c] = gq[k];
            }
            const float2* gb = (const float2*)(g_Bv + (size_t)jb * APAD);
#pragma unroll
            for (int k = tid; k < JCH * 6; k += 128) {       // 768
                int r = k / 6, c = (k % 6) * 2;
                *(float2*)&s_bj[r][c] = gb[k];
            }
        }
        __syncthreads();

        // --- two passes of 2 j's each: j = jb + 64*xp + {0,32} + lane ---
#pragma unroll
        for (int xp = 0; xp < 2; ++xp) {
            const int r0 = 64 * xp + lane;
            u64 h2[2][5];
            float d2s[2], qds[2];
#pragma unroll
            for (int x = 0; x < 2; x++) {
                d2s[x] = 0.f; qds[x] = 0.f;
#pragma unroll
                for (int t = 0; t < 5; t++) {
                    u64 ai = *(const u64*)&s_ai[w][2 * t];
                    h2[x][t] = f2add(ai, *(const u64*)&s_bj[r0 + 32 * x][2 * t]);
                }
            }

#pragma unroll
            for (int kk = 0; kk < 6; ++kk) {
                float4 ci4 = *(const float4*)&s_ciq[w][4 * kk];
                float4 qi4 = *(const float4*)&s_ciq[w][24 + 4 * kk];
                float4 cj[2], qj[2];
#pragma unroll
                for (int x = 0; x < 2; x++) {
                    cj[x] = *(const float4*)&s_cq[r0 + 32 * x][4 * kk];
                    qj[x] = *(const float4*)&s_cq[r0 + 32 * x][24 + 4 * kk];
                }
                const float* cip = &ci4.x; const float* qip = &qi4.x;
#pragma unroll
                for (int e = 0; e < 4; e++) {
                    const int d = 4 * kk + e;
                    u64 av[2];
#pragma unroll
                    for (int x = 0; x < 2; x++) {
                        const float* cjp = &cj[x].x;
                        const float* qjp = &qj[x].x;
                        float df = cip[e] - cjp[e];
                        d2s[x] = fmaf(df, df, d2s[x]);
                        qds[x] = fmaf(qip[e], qjp[e], qds[x]);
                        float ad = fabsf(df);
                        av[x] = pk(ad, ad);
                    }
#pragma unroll
                    for (int t = 0; t < 5; t++) {
                        u64 wv = *(const u64*)&s_w1[d][2 * t];
                        h2[0][t] = f2fma(av[0], wv, h2[0][t]);
                        h2[1][t] = f2fma(av[1], wv, h2[1][t]);
                    }
                }
            }
            // tail features: q_overlap, coord_dist
            u64 qp[2], dp[2];
#pragma unroll
            for (int x = 0; x < 2; x++) {
                float ds = sqrtf(d2s[x]);
                qp[x] = pk(qds[x], qds[x]);
                dp[x] = pk(ds, ds);
            }
#pragma unroll
            for (int t = 0; t < 5; t++) {
                u64 wq = *(const u64*)&s_w1[24][2 * t];
                u64 wd = *(const u64*)&s_w1[25][2 * t];
#pragma unroll
                for (int x = 0; x < 2; x++) {
                    h2[x][t] = f2fma(qp[x], wq, h2[x][t]);
                    h2[x][t] = f2fma(dp[x], wd, h2[x][t]);
                }
            }
            // relu -> hidden scalars
            float ha[2][RD];
#pragma unroll
            for (int x = 0; x < 2; x++) {
#pragma unroll
                for (int t = 0; t < 5; t++) {
                    float lo, hi;
                    upk(lo, hi, h2[x][t]);
                    ha[x][2 * t]     = fmaxf(lo, 0.f);
                    ha[x][2 * t + 1] = fmaxf(hi, 0.f);
                }
            }

            // layer 2
            u64 r2[2][5];
#pragma unroll
            for (int t = 0; t < 5; t++) {
                u64 b2v = pk(b2[2 * t], b2[2 * t + 1]);   // L1-resident LDG.64, uniform
                r2[0][t] = b2v; r2[1][t] = b2v;
            }
#pragma unroll
            for (int rh = 0; rh < RD; rh++) {
                u64 h0 = pk(ha[0][rh], ha[0][rh]);
                u64 h1 = pk(ha[1][rh], ha[1][rh]);
#pragma unroll
                for (int t = 0; t < 5; t++) {
                    u64 wv = *(const u64*)&s_w2[rh][2 * t];
                    r2[0][t] = f2fma(h0, wv, r2[0][t]);
                    r2[1][t] = f2fma(h1, wv, r2[1][t]);
                }
            }
            // relu + masked accumulate
#pragma unroll
            for (int x = 0; x < 2; x++) {
                const bool off = (jb + r0 + 32 * x) != i;
                if (off) {
#pragma unroll
                    for (int t = 0; t < 5; t++) {
                        float v0, v1;
                        upk(v0, v1, r2[x][t]);
                        v0 = fmaxf(v0, 0.f); v1 = fmaxf(v1, 0.f);
                        sacc[2 * t]     += v0;  macc[2 * t]     = fmaxf(macc[2 * t], v0);
                        sacc[2 * t + 1] += v1;  macc[2 * t + 1] = fmaxf(macc[2 * t + 1], v1);
                    }
                }
            }
        }
    }

    // warp reduction across j-lanes (deterministic tree)
#pragma unroll
    for (int c = 0; c < RD; c++) {
#pragma unroll
        for (int o = 16; o > 0; o >>= 1) {
            sacc[c] += __shfl_xor_sync(0xffffffffu, sacc[c], o);
            macc[c] = fmaxf(macc[c], __shfl_xor_sync(0xffffffffu, macc[c], o));
        }
    }
    if (lane == 0) {
        const float inv = 1.0f / (float)(NSEQ - 1);
#pragma unroll
        for (int c = 0; c < RD; c++) {
            out[(size_t)i * RD + c] = sacc[c] * inv;
            out[(size_t)ROWS * RD + (size_t)i * RD + c] = macc[c];
        }
    }
}

// ---------------------------------------------------------------------------
extern "C" void kernel_launch(void* const* d_in, const int* in_sizes, int n_in,
                              void* d_out, int out_size) {
    const float* x     = (const float*)d_in[0];
    const float* q     = (const float*)d_in[1];
    const float* coord = (const float*)d_in[2];
    const float* W1    = (const float*)d_in[3];
    const float* b1    = (const float*)d_in[4];
    const float* W2    = (const float*)d_in[5];
    const float* b2    = (const float*)d_in[6];
    float* out = (float*)d_out;

    precompute_kernel<<<(ROWS + 63) / 64, 64>>>(x, W1, b1);
    pair_kernel<<<ROWS / 4, 128>>>(q, coord, W1, W2, b2, out);
}

// round 13
// speedup vs baseline: 5.2309x; 5.2309x over previous
#include <cuda_runtime.h>

#define DM 24
#define RD 10
#define NSEQ 512
#define NBATCH 8
#define ROWS (NBATCH * NSEQ)          // 4096
#define APAD 12
#define CQS 52                        // padded row stride for staged cj/qj
#define JCH 128                       // j-chunk rows per superiter

typedef unsigned long long u64;

// Scratch (no runtime allocation allowed)
__device__ __align__(16) float g_A[ROWS * APAD];    // x_i @ W1[0:24] + b1
__device__ __align__(16) float g_Bv[ROWS * APAD];   // x_j @ W1[24:48]

// ---------------- f32x2 helpers ----------------
__device__ __forceinline__ u64 pk(float lo, float hi) {
    u64 r; asm("mov.b64 %0, {%1, %2};" : "=l"(r) : "f"(lo), "f"(hi)); return r;
}
__device__ __forceinline__ void upk(float& lo, float& hi, u64 v) {
    asm("mov.b64 {%0, %1}, %2;" : "=f"(lo), "=f"(hi) : "l"(v));
}
__device__ __forceinline__ u64 f2fma(u64 a, u64 b, u64 c) {
    u64 d; asm("fma.rn.f32x2 %0, %1, %2, %3;" : "=l"(d) : "l"(a), "l"(b), "l"(c)); return d;
}
__device__ __forceinline__ u64 f2add(u64 a, u64 b) {
    u64 d; asm("add.rn.f32x2 %0, %1, %2;" : "=l"(d) : "l"(a), "l"(b)); return d;
}
// 16B shared load delivering two u64 (one LDS.128, no repack MOVs)
__device__ __forceinline__ void lds_v2u64(u64& a, u64& b, const float* p) {
    unsigned sa = (unsigned)__cvta_generic_to_shared((const void*)p);
    asm("ld.shared.v2.u64 {%0, %1}, [%2];" : "=l"(a), "=l"(b) : "r"(sa));
}
__device__ __forceinline__ u64 lds_u64(const float* p) {
    unsigned sa = (unsigned)__cvta_generic_to_shared((const void*)p);
    u64 a; asm("ld.shared.u64 %0, [%1];" : "=l"(a) : "r"(sa));
    return a;
}

// ---------------------------------------------------------------------------
// Kernel 1: per-row precompute (vectorized x loads)
// ---------------------------------------------------------------------------
__global__ void precompute_kernel(const float* __restrict__ x,
                                  const float* __restrict__ W1,
                                  const float* __restrict__ b1) {
    int row = blockIdx.x * blockDim.x + threadIdx.x;
    if (row >= ROWS) return;
    float xv[DM];
    {
        const float4* x4 = (const float4*)(x + (size_t)row * DM);
#pragma unroll
        for (int k = 0; k < 6; k++) {
            float4 t = x4[k];
            xv[4*k] = t.x; xv[4*k+1] = t.y; xv[4*k+2] = t.z; xv[4*k+3] = t.w;
        }
    }
    float A[RD], Bv[RD];
#pragma unroll
    for (int r = 0; r < RD; r++) { A[r] = b1[r]; Bv[r] = 0.f; }
#pragma unroll
    for (int d = 0; d < DM; d++) {
        float xd = xv[d];
#pragma unroll
        for (int r = 0; r < RD; r++) {
            A[r]  = fmaf(xd, W1[d * RD + r], A[r]);
            Bv[r] = fmaf(xd, W1[(DM + d) * RD + r], Bv[r]);
        }
    }
#pragma unroll
    for (int r = 0; r < RD; r++) {
        g_A[row * APAD + r]  = A[r];
        g_Bv[row * APAD + r] = Bv[r];
    }
    g_A[row * APAD + 10] = 0.f;  g_A[row * APAD + 11] = 0.f;
    g_Bv[row * APAD + 10] = 0.f; g_Bv[row * APAD + 11] = 0.f;
}

// ---------------------------------------------------------------------------
// Kernel 2: pairwise (R9 structure). 4 warps/block, 1 warp per i, 128-row
// staged j-chunk, 4 j's per lane. Weight loads via ld.shared.v2.u64.
// ---------------------------------------------------------------------------
__global__ __launch_bounds__(128, 4)
void pair_kernel(const float* __restrict__ q,
                 const float* __restrict__ coord,
                 const float* __restrict__ W1,
                 const float* __restrict__ W2,
                 const float* __restrict__ b2,
                 float* __restrict__ out) {
    __shared__ __align__(16) float s_cq[JCH][CQS];  // [r][0:24)=coord_j, [24:48)=q_j (208B stride)
    __shared__ __align__(16) float s_bj[JCH][14];   // B_j rows (56B stride; float2/u64 access only)
    __shared__ __align__(16) float s_w1[26][12];    // [k][r]: k<24 |cdiff| rows, 24=qov, 25=dist (48B rows)
    __shared__ __align__(16) float s_w2[10][12];    // [rh][c] = W2[rh][c] (48B rows)
    __shared__ __align__(16) float s_ciq[4][CQS];   // per-warp: ci (0..23), qi (24..47)
    __shared__ __align__(16) float s_ai[4][12];     // per-warp: A_i

    const int tid = threadIdx.x;
    const int w = tid >> 5, lane = tid & 31;
    const int i = blockIdx.x * 4 + w;
    const int jbase = i & ~(NSEQ - 1);

    // --- one-time fills ---
    for (int idx = tid; idx < 26 * 12; idx += 128) {
        int d = idx / 12, r = idx % 12;
        float v = 0.f;
        if (r < RD) {
            int row = (d < 24) ? (48 + d) : (d == 24 ? 72 : 73);
            v = W1[row * RD + r];
        }
        s_w1[d][r] = v;
    }
    for (int idx = tid; idx < 10 * 12; idx += 128) {
        int rh = idx / 12, c = idx % 12;
        s_w2[rh][c] = (c < RD) ? W2[rh * RD + c] : 0.f;
    }
    if (lane < DM) {
        s_ciq[w][lane]      = coord[(size_t)i * DM + lane];
        s_ciq[w][24 + lane] = q[(size_t)i * DM + lane];
    }
    if (lane < 12) s_ai[w][lane] = g_A[i * APAD + lane];

    u64 b2p[5];
#pragma unroll
    for (int t = 0; t < 5; t++) b2p[t] = pk(b2[2 * t], b2[2 * t + 1]);

    float sacc[RD], macc[RD];
#pragma unroll
    for (int c = 0; c < RD; c++) { sacc[c] = 0.f; macc[c] = 0.f; }

    for (int it = 0; it < NSEQ / JCH; ++it) {
        const int jb = jbase + it * JCH;
        __syncthreads();
        // --- stage 128 j-rows (coalesced) ---
        {
            const float4* gc = (const float4*)(coord + (size_t)jb * DM);
            const float4* gq = (const float4*)(q + (size_t)jb * DM);
#pragma unroll
            for (int k = tid; k < JCH * 6; k += 128) {       // 768
                int r = k / 6, c = (k % 6) * 4;
                *(float4*)&s_cq[r][c]      = gc[k];
                *(float4*)&s_cq[r][24 + c] = gq[k];
            }
            const float2* gb = (const float2*)(g_Bv + (size_t)jb * APAD);
#pragma unroll
            for (int k = tid; k < JCH * 6; k += 128) {       // 768
                int r = k / 6, c = (k % 6) * 2;
                *(float2*)&s_bj[r][c] = gb[k];
            }
        }
        __syncthreads();

        // --- per-lane: 4 pairs (i, jb + lane + 32x) ---
        u64 h2[4][5];
        float d2s[4], qds[4];
#pragma unroll
        for (int x = 0; x < 4; x++) {
            d2s[x] = 0.f; qds[x] = 0.f;
#pragma unroll
            for (int t = 0; t < 5; t++) {
                u64 ai = *(const u64*)&s_ai[w][2 * t];
                h2[x][t] = f2add(ai, *(const u64*)&s_bj[32 * x + lane][2 * t]);
            }
        }

#pragma unroll
        for (int kk = 0; kk < 6; ++kk) {
            float4 ci4 = *(const float4*)&s_ciq[w][4 * kk];
            float4 qi4 = *(const float4*)&s_ciq[w][24 + 4 * kk];
            float4 cj[4], qj[4];
#pragma unroll
            for (int x = 0; x < 4; x++) {
                cj[x] = *(const float4*)&s_cq[32 * x + lane][4 * kk];
                qj[x] = *(const float4*)&s_cq[32 * x + lane][24 + 4 * kk];
            }
            const float* cip = &ci4.x; const float* qip = &qi4.x;
#pragma unroll
            for (int e = 0; e < 4; e++) {
                const int d = 4 * kk + e;
                u64 av[4];
#pragma unroll
                for (int x = 0; x < 4; x++) {
                    const float* cjp = &cj[x].x;
                    const float* qjp = &qj[x].x;
                    float df = cip[e] - cjp[e];
                    d2s[x] = fmaf(df, df, d2s[x]);
                    qds[x] = fmaf(qip[e], qjp[e], qds[x]);
                    float ad = fabsf(df);
                    av[x] = pk(ad, ad);
                }
                // weights: one LDS.128 x2 + LDS.64 (was 5x LDS.64)
                u64 w0, w1v, w2v, w3v, w4v;
                lds_v2u64(w0, w1v, &s_w1[d][0]);
                lds_v2u64(w2v, w3v, &s_w1[d][4]);
                w4v = lds_u64(&s_w1[d][8]);
#pragma unroll
                for (int x = 0; x < 4; x++) {
                    h2[x][0] = f2fma(av[x], w0,  h2[x][0]);
                    h2[x][1] = f2fma(av[x], w1v, h2[x][1]);
                    h2[x][2] = f2fma(av[x], w2v, h2[x][2]);
                    h2[x][3] = f2fma(av[x], w3v, h2[x][3]);
                    h2[x][4] = f2fma(av[x], w4v, h2[x][4]);
                }
            }
        }
        // tail features: q_overlap, coord_dist
        u64 qp[4], dp[4];
#pragma unroll
        for (int x = 0; x < 4; x++) {
            float ds = sqrtf(d2s[x]);
            qp[x] = pk(qds[x], qds[x]);
            dp[x] = pk(ds, ds);
        }
        {
            u64 wq0, wq1, wq2, wq3, wq4;
            lds_v2u64(wq0, wq1, &s_w1[24][0]);
            lds_v2u64(wq2, wq3, &s_w1[24][4]);
            wq4 = lds_u64(&s_w1[24][8]);
            u64 wd0, wd1, wd2, wd3, wd4;
            lds_v2u64(wd0, wd1, &s_w1[25][0]);
            lds_v2u64(wd2, wd3, &s_w1[25][4]);
            wd4 = lds_u64(&s_w1[25][8]);
#pragma unroll
            for (int x = 0; x < 4; x++) {
                h2[x][0] = f2fma(qp[x], wq0, h2[x][0]); h2[x][0] = f2fma(dp[x], wd0, h2[x][0]);
                h2[x][1] = f2fma(qp[x], wq1, h2[x][1]); h2[x][1] = f2fma(dp[x], wd1, h2[x][1]);
                h2[x][2] = f2fma(qp[x], wq2, h2[x][2]); h2[x][2] = f2fma(dp[x], wd2, h2[x][2]);
                h2[x][3] = f2fma(qp[x], wq3, h2[x][3]); h2[x][3] = f2fma(dp[x], wd3, h2[x][3]);
                h2[x][4] = f2fma(qp[x], wq4, h2[x][4]); h2[x][4] = f2fma(dp[x], wd4, h2[x][4]);
            }
        }
        // relu -> hidden scalars
        float ha[4][RD];
#pragma unroll
        for (int x = 0; x < 4; x++) {
#pragma unroll
            for (int t = 0; t < 5; t++) {
                float lo, hi;
                upk(lo, hi, h2[x][t]);
                ha[x][2 * t]     = fmaxf(lo, 0.f);
                ha[x][2 * t + 1] = fmaxf(hi, 0.f);
            }
        }

        // layer 2: each weight load feeds 4 pairs
        u64 r2[4][5];
#pragma unroll
        for (int x = 0; x < 4; x++)
#pragma unroll
            for (int t = 0; t < 5; t++) r2[x][t] = b2p[t];
#pragma unroll
        for (int rh = 0; rh < RD; rh++) {
            u64 hh[4];
#pragma unroll
            for (int x = 0; x < 4; x++) hh[x] = pk(ha[x][rh], ha[x][rh]);
            u64 w0, w1v, w2v, w3v, w4v;
            lds_v2u64(w0, w1v, &s_w2[rh][0]);
            lds_v2u64(w2v, w3v, &s_w2[rh][4]);
            w4v = lds_u64(&s_w2[rh][8]);
#pragma unroll
            for (int x = 0; x < 4; x++) {
                r2[x][0] = f2fma(hh[x], w0,  r2[x][0]);
                r2[x][1] = f2fma(hh[x], w1v, r2[x][1]);
                r2[x][2] = f2fma(hh[x], w2v, r2[x][2]);
                r2[x][3] = f2fma(hh[x], w3v, r2[x][3]);
                r2[x][4] = f2fma(hh[x], w4v, r2[x][4]);
            }
        }
        // relu + masked accumulate
#pragma unroll
        for (int x = 0; x < 4; x++) {
            const bool off = (jb + 32 * x + lane) != i;
            if (off) {
#pragma unroll
                for (int t = 0; t < 5; t++) {
                    float r0, r1;
                    upk(r0, r1, r2[x][t]);
                    r0 = fmaxf(r0, 0.f); r1 = fmaxf(r1, 0.f);
                    sacc[2 * t]     += r0;  macc[2 * t]     = fmaxf(macc[2 * t], r0);
                    sacc[2 * t + 1] += r1;  macc[2 * t + 1] = fmaxf(macc[2 * t + 1], r1);
                }
            }
        }
    }

    // warp reduction across j-lanes (deterministic tree)
#pragma unroll
    for (int c = 0; c < RD; c++) {
#pragma unroll
        for (int o = 16; o > 0; o >>= 1) {
            sacc[c] += __shfl_xor_sync(0xffffffffu, sacc[c], o);
            macc[c] = fmaxf(macc[c], __shfl_xor_sync(0xffffffffu, macc[c], o));
        }
    }
    if (lane == 0) {
        const float inv = 1.0f / (float)(NSEQ - 1);
#pragma unroll
        for (int c = 0; c < RD; c++) {
            out[(size_t)i * RD + c] = sacc[c] * inv;
            out[(size_t)ROWS * RD + (size_t)i * RD + c] = macc[c];
        }
    }
}

// ---------------------------------------------------------------------------
extern "C" void kernel_launch(void* const* d_in, const int* in_sizes, int n_in,
                              void* d_out, int out_size) {
    const float* x     = (const float*)d_in[0];
    const float* q     = (const float*)d_in[1];
    const float* coord = (const float*)d_in[2];
    const float* W1    = (const float*)d_in[3];
    const float* b1    = (const float*)d_in[4];
    const float* W2    = (const float*)d_in[5];
    const float* b2    = (const float*)d_in[6];
    float* out = (float*)d_out;

    precompute_kernel<<<(ROWS + 63) / 64, 64>>>(x, W1, b1);
    pair_kernel<<<ROWS / 4, 128>>>(q, coord, W1, W2, b2, out);
}